// round 1
// baseline (speedup 1.0000x reference)
#include <cuda_runtime.h>
#include <math.h>

#define BB 8
#define TT 256
#define UU 64
#define VV 512
#define U1 (UU + 1)

// Scratch (allocation-free rule: __device__ globals)
__device__ float g_blank[BB * TT * U1];   // log_probs[..., 0]
__device__ float g_emit [BB * TT * UU];   // log_probs[b,t,u,target[b,u]]
__device__ float g_loss [BB];

// ---------------------------------------------------------------------------
// Kernel 1: per-row logsumexp over V=512, emit blank/emit log-probs.
// One warp per (b,t,u) row; 16 floats/lane via 4x float4 -> single DRAM pass.
// ---------------------------------------------------------------------------
__global__ void __launch_bounds__(256) rnnt_softmax_kernel(
    const float* __restrict__ pred, const int* __restrict__ target)
{
    const int warp = (blockIdx.x * blockDim.x + threadIdx.x) >> 5;
    const int lane = threadIdx.x & 31;
    const int rows = BB * TT * U1;
    if (warp >= rows) return;

    const float4* row4 = reinterpret_cast<const float4*>(pred + (size_t)warp * VV);

    float4 v0 = row4[lane];
    float4 v1 = row4[lane + 32];
    float4 v2 = row4[lane + 64];
    float4 v3 = row4[lane + 96];

    // max
    float m = fmaxf(fmaxf(fmaxf(v0.x, v0.y), fmaxf(v0.z, v0.w)),
                    fmaxf(fmaxf(v1.x, v1.y), fmaxf(v1.z, v1.w)));
    m = fmaxf(m, fmaxf(fmaxf(fmaxf(v2.x, v2.y), fmaxf(v2.z, v2.w)),
                       fmaxf(fmaxf(v3.x, v3.y), fmaxf(v3.z, v3.w))));
    #pragma unroll
    for (int o = 16; o > 0; o >>= 1) m = fmaxf(m, __shfl_xor_sync(0xffffffffu, m, o));

    // sum of exp
    float s = 0.f;
    s += __expf(v0.x - m) + __expf(v0.y - m) + __expf(v0.z - m) + __expf(v0.w - m);
    s += __expf(v1.x - m) + __expf(v1.y - m) + __expf(v1.z - m) + __expf(v1.w - m);
    s += __expf(v2.x - m) + __expf(v2.y - m) + __expf(v2.z - m) + __expf(v2.w - m);
    s += __expf(v3.x - m) + __expf(v3.y - m) + __expf(v3.z - m) + __expf(v3.w - m);
    #pragma unroll
    for (int o = 16; o > 0; o >>= 1) s += __shfl_xor_sync(0xffffffffu, s, o);

    const float lse = m + logf(s);

    const int b   = warp / (TT * U1);
    const int rem = warp % (TT * U1);
    const int t   = rem / U1;
    const int u   = rem % U1;

    // blank = element 0 -> lane 0's v0.x
    const float blankv = __shfl_sync(0xffffffffu, v0.x, 0);
    if (lane == 0) g_blank[warp] = blankv - lse;

    if (u < UU) {
        const int tgt = target[b * UU + u];
        // element index of lane's values: e = 4*(lane + 32*i) + k
        float e = 0.f;
        const int base0 = 4 * lane;
        e += (base0 + 0   == tgt) ? v0.x : 0.f;
        e += (base0 + 1   == tgt) ? v0.y : 0.f;
        e += (base0 + 2   == tgt) ? v0.z : 0.f;
        e += (base0 + 3   == tgt) ? v0.w : 0.f;
        e += (base0 + 128 == tgt) ? v1.x : 0.f;
        e += (base0 + 129 == tgt) ? v1.y : 0.f;
        e += (base0 + 130 == tgt) ? v1.z : 0.f;
        e += (base0 + 131 == tgt) ? v1.w : 0.f;
        e += (base0 + 256 == tgt) ? v2.x : 0.f;
        e += (base0 + 257 == tgt) ? v2.y : 0.f;
        e += (base0 + 258 == tgt) ? v2.z : 0.f;
        e += (base0 + 259 == tgt) ? v2.w : 0.f;
        e += (base0 + 384 == tgt) ? v3.x : 0.f;
        e += (base0 + 385 == tgt) ? v3.y : 0.f;
        e += (base0 + 386 == tgt) ? v3.z : 0.f;
        e += (base0 + 387 == tgt) ? v3.w : 0.f;
        #pragma unroll
        for (int o = 16; o > 0; o >>= 1) e += __shfl_xor_sync(0xffffffffu, e, o);
        if (lane == 0) g_emit[b * TT * UU + t * UU + u] = e - lse;
    }
}

// ---------------------------------------------------------------------------
// Kernel 2: wavefront DP over (t,u), one block per batch element.
// blank/emit tiles for this batch resident in dynamic smem (132 KB).
// Double-buffered diagonal row -> one __syncthreads per diagonal.
// ---------------------------------------------------------------------------
__global__ void __launch_bounds__(128) rnnt_dp_kernel(
    const int* __restrict__ pred_len, const int* __restrict__ target_len)
{
    extern __shared__ float sm[];
    float* s_blank = sm;                 // TT*U1 floats
    float* s_emit  = sm + TT * U1;       // TT*UU floats
    __shared__ float s_buf[2][U1];
    __shared__ float s_final;

    const int b   = blockIdx.x;
    const int tid = threadIdx.x;

    for (int i = tid; i < TT * U1; i += blockDim.x) s_blank[i] = g_blank[b * TT * U1 + i];
    for (int i = tid; i < TT * UU; i += blockDim.x) s_emit[i]  = g_emit [b * TT * UU + i];

    const int pl = pred_len[b];
    const int tl = target_len[b];
    __syncthreads();

    const int u = tid;
    float a_prev = 0.f;

    for (int d = 0; d < TT + UU; d++) {
        float* cur  = s_buf[d & 1];
        float* prev = s_buf[(d & 1) ^ 1];
        const int t = d - u;
        if (u <= UU && t >= 0 && t < TT) {
            float val;
            if (t == 0) {
                // row0: pure cumsum of emit at t=0
                val = (u == 0) ? 0.f : prev[u - 1] + s_emit[u - 1];
            } else if (u == 0) {
                val = a_prev + s_blank[(t - 1) * U1];
            } else {
                const float x  = a_prev      + s_blank[(t - 1) * U1 + u];
                const float y  = prev[u - 1] + s_emit [t * UU + (u - 1)];
                const float mm = fmaxf(x, y);
                val = mm + log1pf(__expf(fminf(x, y) - mm));
            }
            a_prev = val;
            cur[u] = val;
            if (u == tl && t == pl - 1) s_final = val;
        }
        __syncthreads();
    }

    if (tid == 0) {
        const float fb = s_blank[(pl - 1) * U1 + tl];
        g_loss[b] = s_final + fb;
    }
}

// ---------------------------------------------------------------------------
// Kernel 3: mean over batch -> scalar output
// ---------------------------------------------------------------------------
__global__ void rnnt_finalize_kernel(float* __restrict__ out)
{
    float s = 0.f;
    #pragma unroll
    for (int b = 0; b < BB; b++) s += g_loss[b];
    out[0] = -s / (float)BB;
}

extern "C" void kernel_launch(void* const* d_in, const int* in_sizes, int n_in,
                              void* d_out, int out_size)
{
    const float* pred       = (const float*)d_in[0];
    const int*   target     = (const int*)  d_in[1];
    const int*   pred_len   = (const int*)  d_in[2];
    const int*   target_len = (const int*)  d_in[3];
    float*       out        = (float*)      d_out;

    (void)in_sizes; (void)n_in; (void)out_size;

    const int rows   = BB * TT * U1;               // 133120 rows
    const int wpb    = 256 / 32;                   // 8 warps per block
    const int blocks = (rows + wpb - 1) / wpb;     // 16640

    const int smem_bytes = (TT * U1 + TT * UU) * (int)sizeof(float);  // 132096
    cudaFuncSetAttribute(rnnt_dp_kernel,
                         cudaFuncAttributeMaxDynamicSharedMemorySize, smem_bytes);

    rnnt_softmax_kernel<<<blocks, 256>>>(pred, target);
    rnnt_dp_kernel<<<BB, 128, smem_bytes>>>(pred_len, target_len);
    rnnt_finalize_kernel<<<1, 1>>>(out);
}